// round 4
// baseline (speedup 1.0000x reference)
#include <cuda_runtime.h>

typedef unsigned long long u64;

// Packed (v,v) pre-scaled weights in the constant bank.
// Layout: [0:15) W1, [15:20) b1, [20:45) 0.5*W2, [45:50) b2, [50:55) 0.5*W3, [55] b3
__constant__ u64 c_w[60];
__device__ u64 g_pack[60];

__global__ void pack_weights_kernel(const float* __restrict__ W1, const float* __restrict__ b1,
                                    const float* __restrict__ W2, const float* __restrict__ b2,
                                    const float* __restrict__ W3, const float* __restrict__ b3)
{
    int i = threadIdx.x;
    if (i >= 60) return;
    float v = 0.0f;
    if      (i < 15) v = W1[i];
    else if (i < 20) v = b1[i - 15];
    else if (i < 45) v = 0.5f * W2[i - 20];
    else if (i < 50) v = b2[i - 45];
    else if (i < 55) v = 0.5f * W3[i - 50];
    else if (i == 55) v = b3[0];
    unsigned int u = __float_as_uint(v);
    g_pack[i] = ((u64)u << 32) | (u64)u;
}

// ---------- packed f32x2 helpers (Blackwell FFMA2 path) ----------
__device__ __forceinline__ u64 pk2(float lo, float hi) {
    u64 r;
    asm("mov.b64 %0, {%1, %2};" : "=l"(r)
        : "r"(__float_as_uint(lo)), "r"(__float_as_uint(hi)));
    return r;
}
__device__ __forceinline__ void upk(u64 a, float& lo, float& hi) {
    unsigned int l_, h_;
    asm("mov.b64 {%0, %1}, %2;" : "=r"(l_), "=r"(h_) : "l"(a));
    lo = __uint_as_float(l_);
    hi = __uint_as_float(h_);
}
__device__ __forceinline__ u64 dfma(u64 a, u64 b, u64 c) {
    u64 d;
    asm("fma.rn.f32x2 %0, %1, %2, %3;" : "=l"(d) : "l"(a), "l"(b), "l"(c));
    return d;
}
__device__ __forceinline__ u64 dmul(u64 a, u64 b) {
    u64 d;
    asm("mul.rn.f32x2 %0, %1, %2;" : "=l"(d) : "l"(a), "l"(b));
    return d;
}
__device__ __forceinline__ u64 dadd(u64 a, u64 b) {
    u64 d;
    asm("add.rn.f32x2 %0, %1, %2;" : "=l"(d) : "l"(a), "l"(b));
    return d;
}
// 2*relu(x) per half, exact: x + |x|  (2x folded into pre-halved W2/W3)
__device__ __forceinline__ u64 drelu2(u64 a) {
    return dadd(a, a & 0x7FFFFFFF7FFFFFFFULL);
}

// Process a packed pair of neighbors; weights from the constant bank.
__device__ __forceinline__ void pair_step(
    u64 ax, u64 ay, u64 az,
    u64 npx, u64 npy, u64 npz,
    u64& vx, u64& vy, u64& vz)
{
    u64 dx = dadd(ax, npx);
    u64 dy = dadd(ay, npy);
    u64 dz = dadd(az, npz);
    u64 d2 = dfma(dx, dx, dfma(dy, dy, dmul(dz, dz)));
    float a, b;
    upk(d2, a, b);
    float ia = rsqrtf(fmaxf(a, 1e-24f));   // matches v/max(||v||,1e-12)
    float ib = rsqrtf(fmaxf(b, 1e-24f));
    u64 inv = pk2(ia, ib);
    u64 nx = dmul(dx, inv);
    u64 ny = dmul(dy, inv);
    u64 nz = dmul(dz, inv);

    // Layer 1
    u64 h0 = dfma(nz, c_w[2],  dfma(ny, c_w[1],  dfma(nx, c_w[0],  c_w[15])));
    u64 h1 = dfma(nz, c_w[5],  dfma(ny, c_w[4],  dfma(nx, c_w[3],  c_w[16])));
    u64 h2 = dfma(nz, c_w[8],  dfma(ny, c_w[7],  dfma(nx, c_w[6],  c_w[17])));
    u64 h3 = dfma(nz, c_w[11], dfma(ny, c_w[10], dfma(nx, c_w[9],  c_w[18])));
    u64 h4 = dfma(nz, c_w[14], dfma(ny, c_w[13], dfma(nx, c_w[12], c_w[19])));
    h0 = drelu2(h0); h1 = drelu2(h1); h2 = drelu2(h2); h3 = drelu2(h3); h4 = drelu2(h4);

    // Layer 2 (weights pre-scaled by 0.5)
    u64 g0 = c_w[45], g1 = c_w[46], g2 = c_w[47], g3 = c_w[48], g4 = c_w[49];
    g0 = dfma(h0, c_w[20], g0); g0 = dfma(h1, c_w[21], g0); g0 = dfma(h2, c_w[22], g0);
    g0 = dfma(h3, c_w[23], g0); g0 = dfma(h4, c_w[24], g0);
    g1 = dfma(h0, c_w[25], g1); g1 = dfma(h1, c_w[26], g1); g1 = dfma(h2, c_w[27], g1);
    g1 = dfma(h3, c_w[28], g1); g1 = dfma(h4, c_w[29], g1);
    g2 = dfma(h0, c_w[30], g2); g2 = dfma(h1, c_w[31], g2); g2 = dfma(h2, c_w[32], g2);
    g2 = dfma(h3, c_w[33], g2); g2 = dfma(h4, c_w[34], g2);
    g3 = dfma(h0, c_w[35], g3); g3 = dfma(h1, c_w[36], g3); g3 = dfma(h2, c_w[37], g3);
    g3 = dfma(h3, c_w[38], g3); g3 = dfma(h4, c_w[39], g3);
    g4 = dfma(h0, c_w[40], g4); g4 = dfma(h1, c_w[41], g4); g4 = dfma(h2, c_w[42], g4);
    g4 = dfma(h3, c_w[43], g4); g4 = dfma(h4, c_w[44], g4);
    g0 = drelu2(g0); g1 = drelu2(g1); g2 = drelu2(g2); g3 = drelu2(g3); g4 = drelu2(g4);

    // Layer 3 (pre-scaled by 0.5)
    u64 w = c_w[55];
    w = dfma(g0, c_w[50], w); w = dfma(g1, c_w[51], w); w = dfma(g2, c_w[52], w);
    w = dfma(g3, c_w[53], w); w = dfma(g4, c_w[54], w);

    // vel += nd * w
    vx = dfma(nx, w, vx);
    vy = dfma(ny, w, vy);
    vz = dfma(nz, w, vz);
}

// Block = 128 threads = 128 points. Stage the block's 48KB neighbor slab into
// smem with fully-coalesced LDG.128, then compute from smem with a padded
// (25-float4 = 400B) per-point stride -> conflict-free LDS.128.
__global__ void __launch_bounds__(128)
velvec_kernel(const float* __restrict__ pos, const float* __restrict__ nbr,
              float* __restrict__ out, int N)
{
    extern __shared__ float4 sm[];   // 128 * 25 float4 = 51200 B

    int tid = threadIdx.x;
    int base = blockIdx.x * 128;
    int npts = N - base; if (npts > 128) npts = 128;
    int cnt = npts * 24;

    const float4* g = reinterpret_cast<const float4*>(nbr) + (size_t)base * 24;
#pragma unroll 4
    for (int i = tid; i < cnt; i += 128) {
        int p = i / 24;
        int j = i - p * 24;
        sm[p * 25 + j] = g[i];
    }
    __syncthreads();

    if (tid >= npts) return;
    int n = base + tid;

    float px = pos[3 * n + 0];
    float py = pos[3 * n + 1];
    float pz = pos[3 * n + 2];
    u64 npx = pk2(-px, -px), npy = pk2(-py, -py), npz = pk2(-pz, -pz);

    u64 vx = 0ULL, vy = 0ULL, vz = 0ULL;  // (+0.f, +0.f)

    const float4* row = sm + tid * 25;

#pragma unroll 2
    for (int gi = 0; gi < 8; gi++) {
        float4 q0 = row[3 * gi + 0];  // x0 y0 z0 x1
        float4 q1 = row[3 * gi + 1];  // y1 z1 x2 y2
        float4 q2 = row[3 * gi + 2];  // z2 x3 y3 z3
        pair_step(pk2(q0.x, q0.w), pk2(q0.y, q1.x), pk2(q0.z, q1.y),
                  npx, npy, npz, vx, vy, vz);
        pair_step(pk2(q1.z, q2.y), pk2(q1.w, q2.z), pk2(q2.x, q2.w),
                  npx, npy, npz, vx, vy, vz);
    }

    float x0, x1, y0, y1, z0, z1;
    upk(vx, x0, x1); upk(vy, y0, y1); upk(vz, z0, z1);
    float fx = x0 + x1, fy = y0 + y1, fz = z0 + z1;

    float d2 = fmaf(fx, fx, fmaf(fy, fy, fz * fz));
    d2 = fmaxf(d2, 1e-24f);
    float r = rsqrtf(d2);
    r = r * fmaf(-0.5f * d2 * r, r, 1.5f);  // one Newton step for the final normalize

    out[3 * n + 0] = fx * r;
    out[3 * n + 1] = fy * r;
    out[3 * n + 2] = fz * r;
}

extern "C" void kernel_launch(void* const* d_in, const int* in_sizes, int n_in,
                              void* d_out, int out_size)
{
    const float* pos = (const float*)d_in[0];
    const float* nbr = (const float*)d_in[1];
    const float* W1  = (const float*)d_in[2];
    const float* b1  = (const float*)d_in[3];
    const float* W2  = (const float*)d_in[4];
    const float* b2  = (const float*)d_in[5];
    const float* W3  = (const float*)d_in[6];
    const float* b3  = (const float*)d_in[7];
    float* out = (float*)d_out;

    static bool attr_set = false;
    if (!attr_set) {
        cudaFuncSetAttribute(velvec_kernel,
                             cudaFuncAttributeMaxDynamicSharedMemorySize, 51200);
        attr_set = true;
    }

    // 1) pack + pre-scale weights into a __device__ buffer
    pack_weights_kernel<<<1, 64>>>(W1, b1, W2, b2, W3, b3);

    // 2) D2D async copy into the constant bank (graph-capturable memcpy node)
    void* src = nullptr;
    cudaGetSymbolAddress(&src, g_pack);
    cudaMemcpyToSymbolAsync(c_w, src, 60 * sizeof(u64), 0,
                            cudaMemcpyDeviceToDevice, 0);

    // 3) main kernel
    int N = in_sizes[0] / 3;  // positions is [N,3]
    int blocks = (N + 127) / 128;
    velvec_kernel<<<blocks, 128, 51200>>>(pos, nbr, out, N);
}

// round 5
// speedup vs baseline: 1.0705x; 1.0705x over previous
#include <cuda_runtime.h>
#include <cstdint>

typedef unsigned long long u64;

// ---------- packed f32x2 helpers ----------
__device__ __forceinline__ u64 pk2(float lo, float hi) {
    u64 r;
    asm("mov.b64 %0, {%1, %2};" : "=l"(r)
        : "r"(__float_as_uint(lo)), "r"(__float_as_uint(hi)));
    return r;
}
__device__ __forceinline__ void upk(u64 a, float& lo, float& hi) {
    unsigned int l_, h_;
    asm("mov.b64 {%0, %1}, %2;" : "=r"(l_), "=r"(h_) : "l"(a));
    lo = __uint_as_float(l_);
    hi = __uint_as_float(h_);
}
__device__ __forceinline__ u64 dfma(u64 a, u64 b, u64 c) {
    u64 d;
    asm("fma.rn.f32x2 %0, %1, %2, %3;" : "=l"(d) : "l"(a), "l"(b), "l"(c));
    return d;
}
__device__ __forceinline__ u64 dmul(u64 a, u64 b) {
    u64 d;
    asm("mul.rn.f32x2 %0, %1, %2;" : "=l"(d) : "l"(a), "l"(b));
    return d;
}
__device__ __forceinline__ u64 dadd(u64 a, u64 b) {
    u64 d;
    asm("add.rn.f32x2 %0, %1, %2;" : "=l"(d) : "l"(a), "l"(b));
    return d;
}
// 2*relu(x) per half, exact: x + |x| (2x folded into pre-halved W2/W3)
__device__ __forceinline__ u64 drelu2(u64 a) {
    return dadd(a, a & 0x7FFFFFFF7FFFFFFFULL);
}
__device__ __forceinline__ uint32_t smem_u32(const void* p) {
    uint32_t a;
    asm("{ .reg .u64 t; cvta.to.shared.u64 t, %1; cvt.u32.u64 %0, t; }"
        : "=r"(a) : "l"(p));
    return a;
}
// paired weight load (LDS.128): two packed u64 weights per instruction
__device__ __forceinline__ void ldsw2(uint32_t addr, u64& a, u64& b) {
    asm("ld.shared.v2.u64 {%0, %1}, [%2];" : "=l"(a), "=l"(b) : "r"(addr));
}

// ---------- mbarrier / bulk-copy ----------
__device__ __forceinline__ void mbar_init(uint32_t mb, uint32_t cnt) {
    asm volatile("mbarrier.init.shared.b64 [%0], %1;" :: "r"(mb), "r"(cnt) : "memory");
}
__device__ __forceinline__ void mbar_expect_tx(uint32_t mb, uint32_t bytes) {
    asm volatile("mbarrier.arrive.expect_tx.shared.b64 _, [%0], %1;"
                 :: "r"(mb), "r"(bytes) : "memory");
}
__device__ __forceinline__ void mbar_wait(uint32_t mb, uint32_t parity) {
    asm volatile(
        "{\n\t"
        ".reg .pred P;\n\t"
        "WL_%=:\n\t"
        "mbarrier.try_wait.parity.acquire.cta.shared::cta.b64 P, [%0], %1, 0x989680;\n\t"
        "@P bra.uni WD_%=;\n\t"
        "bra.uni WL_%=;\n\t"
        "WD_%=:\n\t"
        "}" :: "r"(mb), "r"(parity) : "memory");
}
__device__ __forceinline__ void bulk_g2s(uint32_t dst, const void* src,
                                         uint32_t bytes, uint32_t mb) {
    asm volatile(
        "cp.async.bulk.shared::cluster.global.mbarrier::complete_tx::bytes "
        "[%0], [%1], %2, [%3];"
        :: "r"(dst), "l"(src), "r"(bytes), "r"(mb) : "memory");
}

// Weight smem layout (u64 packed (v,v)), ordered for paired loads:
//  [4j+0..4j+3]  = W1[j,0], W1[j,1], W1[j,2], b1[j]          (j=0..4)
//  [20+6j..+5]   = .5*W2[j,0..4], b2[j]                       (j=0..4)
//  [50..55]      = .5*W3[0..4], b3
// Process one packed pair of neighbors (2 neighbors in the 2 f32x2 halves).
__device__ __forceinline__ void pair_step(
    u64 ax, u64 ay, u64 az,
    u64 npx, u64 npy, u64 npz,
    uint32_t swb,
    u64& vx, u64& vy, u64& vz)
{
    u64 dx = dadd(ax, npx);
    u64 dy = dadd(ay, npy);
    u64 dz = dadd(az, npz);
    u64 d2 = dfma(dx, dx, dfma(dy, dy, dmul(dz, dz)));
    float a, b;
    upk(d2, a, b);
    float ia = rsqrtf(fmaxf(a, 1e-24f));   // matches v/max(||v||,1e-12)
    float ib = rsqrtf(fmaxf(b, 1e-24f));

    // Layer 1 on the UNNORMALIZED diff (overlaps the MUFU rsqrt):
    u64 wa, wb, wc, B0, B1, B2, B3, B4;
    u64 u0, u1, u2, u3, u4;
    ldsw2(swb + 0 * 8, wa, wb); ldsw2(swb + 2 * 8, wc, B0);
    u0 = dfma(dz, wc, dfma(dy, wb, dmul(dx, wa)));
    ldsw2(swb + 4 * 8, wa, wb); ldsw2(swb + 6 * 8, wc, B1);
    u1 = dfma(dz, wc, dfma(dy, wb, dmul(dx, wa)));
    ldsw2(swb + 8 * 8, wa, wb); ldsw2(swb + 10 * 8, wc, B2);
    u2 = dfma(dz, wc, dfma(dy, wb, dmul(dx, wa)));
    ldsw2(swb + 12 * 8, wa, wb); ldsw2(swb + 14 * 8, wc, B3);
    u3 = dfma(dz, wc, dfma(dy, wb, dmul(dx, wa)));
    ldsw2(swb + 16 * 8, wa, wb); ldsw2(swb + 18 * 8, wc, B4);
    u4 = dfma(dz, wc, dfma(dy, wb, dmul(dx, wa)));

    u64 inv = pk2(ia, ib);
    u64 h0 = drelu2(dfma(u0, inv, B0));
    u64 h1 = drelu2(dfma(u1, inv, B1));
    u64 h2 = drelu2(dfma(u2, inv, B2));
    u64 h3 = drelu2(dfma(u3, inv, B3));
    u64 h4 = drelu2(dfma(u4, inv, B4));

    // Layer 2 (weights pre-scaled by 0.5)
    u64 wd, we, bj;
    u64 g0, g1, g2, g3, g4;
#define L2ROW(G, OFF)                                                       \
    ldsw2(swb + (OFF) * 8, wa, wb); ldsw2(swb + ((OFF) + 2) * 8, wc, wd);   \
    ldsw2(swb + ((OFF) + 4) * 8, we, bj);                                   \
    G = dfma(h0, wa, bj); G = dfma(h1, wb, G); G = dfma(h2, wc, G);         \
    G = dfma(h3, wd, G);  G = dfma(h4, we, G); G = drelu2(G);
    L2ROW(g0, 20) L2ROW(g1, 26) L2ROW(g2, 32) L2ROW(g3, 38) L2ROW(g4, 44)
#undef L2ROW

    // Layer 3 (pre-scaled by 0.5)
    ldsw2(swb + 50 * 8, wa, wb);
    ldsw2(swb + 52 * 8, wc, wd);
    ldsw2(swb + 54 * 8, we, bj);
    u64 wgt = dfma(g0, wa, bj);
    wgt = dfma(g1, wb, wgt); wgt = dfma(g2, wc, wgt);
    wgt = dfma(g3, wd, wgt); wgt = dfma(g4, we, wgt);

    // vel += nd * w == d * (inv * w)
    u64 wi = dmul(wgt, inv);
    vx = dfma(dx, wi, vx);
    vy = dfma(dy, wi, vy);
    vz = dfma(dz, wi, vz);
}

// Persistent, double-buffered pipeline. 256 threads; tile = 128 points (48KB
// slab via cp.async.bulk). 2 threads per point: lanes l and l^16 take 16
// neighbors each; shfl_xor(16) combines.
__global__ void __launch_bounds__(256, 2)
velvec_kernel(const float* __restrict__ pos, const float* __restrict__ nbr,
              const float* __restrict__ W1, const float* __restrict__ b1,
              const float* __restrict__ W2, const float* __restrict__ b2,
              const float* __restrict__ W3, const float* __restrict__ b3,
              float* __restrict__ out, int N, int ntiles)
{
    extern __shared__ float4 slab[];           // 2 * 3072 float4 = 98304 B
    __shared__ __align__(16) u64 sw[56];
    __shared__ __align__(8) u64 mbar[2];

    int tid = threadIdx.x;

    // ---- weights: load + pack + pre-scale once per block ----
    if (tid < 56) {
        float v;
        if (tid < 20) {
            int j = tid >> 2, i = tid & 3;
            v = (i < 3) ? __ldg(W1 + 3 * j + i) : __ldg(b1 + j);
        } else if (tid < 50) {
            int t = tid - 20, j = t / 6, i = t - 6 * j;
            v = (i < 5) ? 0.5f * __ldg(W2 + 5 * j + i) : __ldg(b2 + j);
        } else if (tid < 55) {
            v = 0.5f * __ldg(W3 + tid - 50);
        } else {
            v = __ldg(b3);
        }
        unsigned int u = __float_as_uint(v);
        sw[tid] = ((u64)u << 32) | (u64)u;
    }
    if (tid == 0) { mbar_init(smem_u32(&mbar[0]), 1); mbar_init(smem_u32(&mbar[1]), 1); }
    __syncthreads();
    asm volatile("fence.proxy.async;" ::: "memory");

    uint32_t mb0 = smem_u32(&mbar[0]);
    uint32_t mb1 = smem_u32(&mbar[1]);
    uint32_t swb = smem_u32(sw);
    uint32_t slb = smem_u32(slab);
    const char* gnbr = (const char*)nbr;

    int b = blockIdx.x, G = gridDim.x;

    // prologue: prefetch first two tiles
    if (tid == 0) {
#pragma unroll
        for (int k = 0; k < 2; k++) {
            int t = b + k * G;
            if (t < ntiles) {
                int base = t * 128;
                int npts = N - base; if (npts > 128) npts = 128;
                uint32_t bytes = (uint32_t)npts * 384u;
                uint32_t mb = k ? mb1 : mb0;
                mbar_expect_tx(mb, bytes);
                bulk_g2s(slb + (uint32_t)k * 49152u, gnbr + (size_t)base * 384, bytes, mb);
            }
        }
    }

    int w = tid >> 5;
    int l = tid & 31;
    int q = l & 15;        // point offset within warp's 16 points
    int half = l >> 4;     // neighbor half
    int rot = l & 3;

    int ph0 = 0, ph1 = 0;
    int k = 0;
    for (int t = b; t < ntiles; t += G, k++) {
        int s = k & 1;
        if (s) { mbar_wait(mb1, ph1); ph1 ^= 1; }
        else   { mbar_wait(mb0, ph0); ph0 ^= 1; }

        int base = t * 128;
        int npts = N - base; if (npts > 128) npts = 128;
        int pt = w * 16 + q;
        int n = base + pt;

        float px = 0.f, py = 0.f, pz = 0.f;
        if (pt < npts) {
            px = __ldg(pos + 3 * n + 0);
            py = __ldg(pos + 3 * n + 1);
            pz = __ldg(pos + 3 * n + 2);
        }
        u64 npx = pk2(-px, -px), npy = pk2(-py, -py), npz = pk2(-pz, -pz);
        u64 vx = 0ULL, vy = 0ULL, vz = 0ULL;

        const float4* row = slab + s * 3072 + pt * 24 + half * 12;
#pragma unroll
        for (int g = 0; g < 4; g++) {
            int gr = (g + rot) & 3;        // bank-stagger; reorders fp sum (ok)
            float4 q0 = row[3 * gr + 0];   // x0 y0 z0 x1
            float4 q1 = row[3 * gr + 1];   // y1 z1 x2 y2
            float4 q2 = row[3 * gr + 2];   // z2 x3 y3 z3
            pair_step(pk2(q0.x, q0.w), pk2(q0.y, q1.x), pk2(q0.z, q1.y),
                      npx, npy, npz, swb, vx, vy, vz);
            pair_step(pk2(q1.z, q2.y), pk2(q1.w, q2.z), pk2(q2.x, q2.w),
                      npx, npy, npz, swb, vx, vy, vz);
        }

        float x0, x1, y0, y1, z0, z1;
        upk(vx, x0, x1); upk(vy, y0, y1); upk(vz, z0, z1);
        float fx = x0 + x1, fy = y0 + y1, fz = z0 + z1;
        fx += __shfl_xor_sync(0xFFFFFFFFu, fx, 16);
        fy += __shfl_xor_sync(0xFFFFFFFFu, fy, 16);
        fz += __shfl_xor_sync(0xFFFFFFFFu, fz, 16);

        if (half == 0 && pt < npts) {
            float d2 = fmaf(fx, fx, fmaf(fy, fy, fz * fz));
            d2 = fmaxf(d2, 1e-24f);
            float r = rsqrtf(d2);
            r = r * fmaf(-0.5f * d2 * r, r, 1.5f);  // one Newton step
            out[3 * n + 0] = fx * r;
            out[3 * n + 1] = fy * r;
            out[3 * n + 2] = fz * r;
        }

        __syncthreads();   // all lanes done reading buffer s
        if (tid == 0) {
            int t2 = t + 2 * G;
            if (t2 < ntiles) {
                int base2 = t2 * 128;
                int npts2 = N - base2; if (npts2 > 128) npts2 = 128;
                uint32_t bytes = (uint32_t)npts2 * 384u;
                uint32_t mb = s ? mb1 : mb0;
                mbar_expect_tx(mb, bytes);
                bulk_g2s(slb + (uint32_t)s * 49152u, gnbr + (size_t)base2 * 384,
                         bytes, mb);
            }
        }
    }
}

extern "C" void kernel_launch(void* const* d_in, const int* in_sizes, int n_in,
                              void* d_out, int out_size)
{
    const float* pos = (const float*)d_in[0];
    const float* nbr = (const float*)d_in[1];
    const float* W1  = (const float*)d_in[2];
    const float* b1  = (const float*)d_in[3];
    const float* W2  = (const float*)d_in[4];
    const float* b2  = (const float*)d_in[5];
    const float* W3  = (const float*)d_in[6];
    const float* b3  = (const float*)d_in[7];
    float* out = (float*)d_out;

    static bool attr_set = false;
    if (!attr_set) {
        cudaFuncSetAttribute(velvec_kernel,
                             cudaFuncAttributeMaxDynamicSharedMemorySize, 98304);
        attr_set = true;
    }

    int N = in_sizes[0] / 3;           // positions is [N,3]
    int ntiles = (N + 127) / 128;
    int grid = 296;                     // 2 persistent blocks per SM
    if (grid > ntiles) grid = ntiles;
    velvec_kernel<<<grid, 256, 98304>>>(pos, nbr, W1, b1, W2, b2, W3, b3,
                                        out, N, ntiles);
}